// round 2
// baseline (speedup 1.0000x reference)
#include <cuda_runtime.h>
#include <math.h>

#define Bq   256
#define Tq   512
#define Dq   256
#define Hq   512
#define F1q  128
#define Oq   64
#define BHq  (Bq*Hq)
#define NBLK_SCAN 96

// ---------------- scratch (device globals: allocation-free rule) ----------------
__device__ float g_pre0[(size_t)Bq*Tq*Hq];   // [B*T, H] = 256 MB
__device__ float g_h0[2*BHq];                // double-buffered layer0 state
__device__ float g_p1[2*BHq];                // double-buffered layer1 input preact
__device__ float g_h1[2*BHq];                // double-buffered layer1 state
__device__ float g_z1[Bq*F1q];
__device__ unsigned g_count;
__device__ volatile unsigned g_sense;

// ---------------- grid barrier (sense-reversing, 1 wave resident) ----------------
__device__ __forceinline__ void grid_barrier(unsigned nblk, unsigned &sense)
{
    __syncthreads();
    if (threadIdx.x == 0) {
        unsigned ns = sense ^ 1u;
        if (atomicAdd(&g_count, 1u) == nblk - 1u) {
            g_count = 0u;
            __threadfence();
            g_sense = ns;
        } else {
            while (g_sense != ns) { __nanosleep(64); }
        }
    }
    __syncthreads();
    sense ^= 1u;
}

// ---------------- 64x64 fp32 GEMM tile core:  C = A(M,K) * W(N,K)^T ----------------
// 256 threads, thread (tx,ty) computes 4x4 at (ty*4, tx*4). K multiple of 16.
__device__ __forceinline__ void gemm64(const float* __restrict__ A, int lda, int m0,
                                       const float* __restrict__ W, int ldw, int n0,
                                       int K, bool cgA,
                                       float* sA, float* sW, float acc[4][4])
{
    const int tid  = threadIdx.x;
    const int tx   = tid & 15, ty = tid >> 4;
    const int lrow = tid >> 2;          // 0..63
    const int lcg  = (tid & 3) << 2;    // 0,4,8,12
    const float* ap = A + (size_t)(m0 + lrow) * lda + lcg;
    const float* wp = W + (size_t)(n0 + lrow) * ldw + lcg;

    for (int kc = 0; kc < K; kc += 16) {
        float4 av = cgA ? __ldcg((const float4*)(ap + kc)) : *(const float4*)(ap + kc);
        float4 wv = *(const float4*)(wp + kc);
        sA[(lcg+0)*68 + lrow] = av.x;
        sA[(lcg+1)*68 + lrow] = av.y;
        sA[(lcg+2)*68 + lrow] = av.z;
        sA[(lcg+3)*68 + lrow] = av.w;
        sW[(lcg+0)*68 + lrow] = wv.x;
        sW[(lcg+1)*68 + lrow] = wv.y;
        sW[(lcg+2)*68 + lrow] = wv.z;
        sW[(lcg+3)*68 + lrow] = wv.w;
        __syncthreads();
        #pragma unroll
        for (int k = 0; k < 16; ++k) {
            float4 a = *(const float4*)&sA[k*68 + (ty<<2)];
            float4 w = *(const float4*)&sW[k*68 + (tx<<2)];
            acc[0][0] += a.x*w.x; acc[0][1] += a.x*w.y; acc[0][2] += a.x*w.z; acc[0][3] += a.x*w.w;
            acc[1][0] += a.y*w.x; acc[1][1] += a.y*w.y; acc[1][2] += a.y*w.z; acc[1][3] += a.y*w.w;
            acc[2][0] += a.z*w.x; acc[2][1] += a.z*w.y; acc[2][2] += a.z*w.z; acc[2][3] += a.z*w.w;
            acc[3][0] += a.w*w.x; acc[3][1] += a.w*w.y; acc[3][2] += a.w*w.z; acc[3][3] += a.w*w.w;
        }
        __syncthreads();
    }
}

// ---------------- kernel A: pre0 = x @ W_ih0^T + b_ih0 + b_hh0 ----------------
__global__ void __launch_bounds__(256) k_pre0(const float* __restrict__ x,
                                              const float* __restrict__ Wih,
                                              const float* __restrict__ bih,
                                              const float* __restrict__ bhh)
{
    __shared__ float sA[16*68], sW[16*68];
    float acc[4][4] = {};
    const int m0 = blockIdx.y << 6;   // over B*T (2048 tiles)
    const int n0 = blockIdx.x << 6;   // over H (8 tiles)
    gemm64(x, Dq, m0, Wih, Dq, n0, Dq, false, sA, sW, acc);

    const int tx = threadIdx.x & 15, ty = threadIdx.x >> 4;
    const int col = n0 + (tx << 2);
    float4 b1 = *(const float4*)(bih + col);
    float4 b2 = *(const float4*)(bhh + col);
    #pragma unroll
    for (int i = 0; i < 4; ++i) {
        int row = m0 + (ty << 2) + i;
        float4 o;
        o.x = acc[i][0] + b1.x + b2.x;
        o.y = acc[i][1] + b1.y + b2.y;
        o.z = acc[i][2] + b1.z + b2.z;
        o.w = acc[i][3] + b1.w + b2.w;
        *(float4*)(g_pre0 + (size_t)row*Hq + col) = o;
    }
}

// ---------------- reset barrier state (runs before each scan) ----------------
__global__ void k_reset()
{
    g_count = 0u;
    g_sense = 0u;
}

// ---------------- kernel B: persistent pipelined 2-layer scan ----------------
// 96 blocks = 3 groups x 32 tiles (64x64). 514 rounds, grid barrier each round.
//  G0 @ round r (r<T):    h0_r    = tanh(pre0[:,r,:] + h0_{r-1} @ W_hh0^T)
//  G1 @ round r (1<=r<=T):p1_{r-1}= h0_{r-1} @ W_ih1^T + b_ih1 + b_hh1
//  G2 @ round r (r>=2):   h1_{r-2}= tanh(p1_{r-2} + h1_{r-3} @ W_hh1^T)
__global__ void __launch_bounds__(256) k_scan(const float* __restrict__ Whh0,
                                              const float* __restrict__ Wih1,
                                              const float* __restrict__ bih1,
                                              const float* __restrict__ bhh1,
                                              const float* __restrict__ Whh1)
{
    __shared__ float sA[16*68], sW[16*68];
    const int tid   = threadIdx.x;
    const int blk   = blockIdx.x;
    const int group = blk >> 5;        // 0,1,2
    const int tile  = blk & 31;
    const int m0    = (tile & 3) << 6; // B rows
    const int n0    = (tile >> 2) << 6;// H cols
    const int tx = tid & 15, ty = tid >> 4;
    unsigned sense = 0u;

    // zero the t=-1 parity buffers (buf index ((-1)&1)==1)
    for (int i = blk*256 + tid; i < BHq; i += NBLK_SCAN*256) {
        g_h0[BHq + i] = 0.f;
        g_h1[BHq + i] = 0.f;
    }
    __threadfence();
    grid_barrier(gridDim.x, sense);

    for (int r = 0; r < Tq + 2; ++r) {
        if (group == 0) {
            if (r < Tq) {
                float acc[4][4] = {};
                const float* A = g_h0 + (size_t)((r+1)&1)*BHq;   // h0_{r-1}
                gemm64(A, Hq, m0, Whh0, Hq, n0, Hq, true, sA, sW, acc);
                float* dst = g_h0 + (size_t)(r&1)*BHq;
                const int col = n0 + (tx << 2);
                #pragma unroll
                for (int i = 0; i < 4; ++i) {
                    int row = m0 + (ty << 2) + i;
                    float4 p = __ldcg((const float4*)(g_pre0 + ((size_t)row*Tq + r)*Hq + col));
                    float4 o;
                    o.x = tanhf(acc[i][0] + p.x);
                    o.y = tanhf(acc[i][1] + p.y);
                    o.z = tanhf(acc[i][2] + p.z);
                    o.w = tanhf(acc[i][3] + p.w);
                    *(float4*)(dst + (size_t)row*Hq + col) = o;
                }
            }
        } else if (group == 1) {
            if (r >= 1 && r <= Tq) {
                float acc[4][4] = {};
                const float* A = g_h0 + (size_t)((r+1)&1)*BHq;   // h0_{r-1}
                gemm64(A, Hq, m0, Wih1, Hq, n0, Hq, true, sA, sW, acc);
                float* dst = g_p1 + (size_t)((r+1)&1)*BHq;       // p1_{r-1}
                const int col = n0 + (tx << 2);
                float4 b1 = *(const float4*)(bih1 + col);
                float4 b2 = *(const float4*)(bhh1 + col);
                #pragma unroll
                for (int i = 0; i < 4; ++i) {
                    int row = m0 + (ty << 2) + i;
                    float4 o;
                    o.x = acc[i][0] + b1.x + b2.x;
                    o.y = acc[i][1] + b1.y + b2.y;
                    o.z = acc[i][2] + b1.z + b2.z;
                    o.w = acc[i][3] + b1.w + b2.w;
                    *(float4*)(dst + (size_t)row*Hq + col) = o;
                }
            }
        } else {
            if (r >= 2) {
                const int t = r - 2;
                float acc[4][4] = {};
                const float* A = g_h1 + (size_t)((t+1)&1)*BHq;   // h1_{t-1}
                gemm64(A, Hq, m0, Whh1, Hq, n0, Hq, true, sA, sW, acc);
                float* dst = g_h1 + (size_t)(t&1)*BHq;
                const float* pin = g_p1 + (size_t)(t&1)*BHq;
                const int col = n0 + (tx << 2);
                #pragma unroll
                for (int i = 0; i < 4; ++i) {
                    int row = m0 + (ty << 2) + i;
                    float4 p = __ldcg((const float4*)(pin + (size_t)row*Hq + col));
                    float4 o;
                    o.x = tanhf(acc[i][0] + p.x);
                    o.y = tanhf(acc[i][1] + p.y);
                    o.z = tanhf(acc[i][2] + p.z);
                    o.w = tanhf(acc[i][3] + p.w);
                    *(float4*)(dst + (size_t)row*Hq + col) = o;
                }
            }
        }
        __threadfence();
        grid_barrier(gridDim.x, sense);
    }
}

// ---------------- head: z1 = relu(h1_last @ Wf1^T + bf1) ----------------
__global__ void __launch_bounds__(256) k_fc1(const float* __restrict__ Wf1,
                                             const float* __restrict__ bf1)
{
    __shared__ float sA[16*68], sW[16*68];
    float acc[4][4] = {};
    const int m0 = blockIdx.y << 6;   // B (4)
    const int n0 = blockIdx.x << 6;   // F1 (2)
    const float* A = g_h1 + (size_t)((Tq-1)&1)*BHq;  // h1_{511} lives in buf 1
    gemm64(A, Hq, m0, Wf1, Hq, n0, Hq, false, sA, sW, acc);

    const int tx = threadIdx.x & 15, ty = threadIdx.x >> 4;
    const int col = n0 + (tx << 2);
    float4 b = *(const float4*)(bf1 + col);
    #pragma unroll
    for (int i = 0; i < 4; ++i) {
        int row = m0 + (ty << 2) + i;
        float4 o;
        o.x = fmaxf(acc[i][0] + b.x, 0.f);
        o.y = fmaxf(acc[i][1] + b.y, 0.f);
        o.z = fmaxf(acc[i][2] + b.z, 0.f);
        o.w = fmaxf(acc[i][3] + b.w, 0.f);
        *(float4*)(g_z1 + (size_t)row*F1q + col) = o;
    }
}

// ---------------- head: out = z1 @ Wf2^T + bf2 ----------------
__global__ void __launch_bounds__(256) k_fc2(const float* __restrict__ Wf2,
                                             const float* __restrict__ bf2,
                                             float* __restrict__ out)
{
    __shared__ float sA[16*68], sW[16*68];
    float acc[4][4] = {};
    const int m0 = blockIdx.y << 6;   // B (4)
    const int n0 = 0;                 // O = 64, single tile
    gemm64(g_z1, F1q, m0, Wf2, F1q, n0, F1q, false, sA, sW, acc);

    const int tx = threadIdx.x & 15, ty = threadIdx.x >> 4;
    const int col = n0 + (tx << 2);
    float4 b = *(const float4*)(bf2 + col);
    #pragma unroll
    for (int i = 0; i < 4; ++i) {
        int row = m0 + (ty << 2) + i;
        float4 o;
        o.x = acc[i][0] + b.x;
        o.y = acc[i][1] + b.y;
        o.z = acc[i][2] + b.z;
        o.w = acc[i][3] + b.w;
        *(float4*)(out + (size_t)row*Oq + col) = o;
    }
}

// ---------------- launch ----------------
extern "C" void kernel_launch(void* const* d_in, const int* in_sizes, int n_in,
                              void* d_out, int out_size)
{
    (void)in_sizes; (void)n_in; (void)out_size;
    const float* x    = (const float*)d_in[0];
    const float* Wih0 = (const float*)d_in[1];
    const float* Whh0 = (const float*)d_in[2];
    const float* bih0 = (const float*)d_in[3];
    const float* bhh0 = (const float*)d_in[4];
    const float* Wih1 = (const float*)d_in[5];
    const float* Whh1 = (const float*)d_in[6];
    const float* bih1 = (const float*)d_in[7];
    const float* bhh1 = (const float*)d_in[8];
    const float* Wf1  = (const float*)d_in[9];
    const float* bf1  = (const float*)d_in[10];
    const float* Wf2  = (const float*)d_in[11];
    const float* bf2  = (const float*)d_in[12];
    float* out = (float*)d_out;

    k_pre0<<<dim3(Hq/64, (Bq*Tq)/64), 256>>>(x, Wih0, bih0, bhh0);
    k_reset<<<1, 1>>>();
    k_scan<<<NBLK_SCAN, 256>>>(Whh0, Wih1, bih1, bhh1, Whh1);
    k_fc1<<<dim3(F1q/64, Bq/64), 256>>>(Wf1, bf1);
    k_fc2<<<dim3(1, Bq/64), 256>>>(Wf2, bf2, out);
}

// round 4
// speedup vs baseline: 1.3138x; 1.3138x over previous
#include <cuda_runtime.h>
#include <math.h>

#define Bq   256
#define Tq   512
#define Dq   256
#define Hq   512
#define F1q  128
#define Oq   64
#define BHq  (Bq*Hq)
#define NBLK_SCAN 96
#define SCH  (16*68)   // one smem chunk: 16 k-slices x 68-stride

// ---------------- scratch (device globals: allocation-free rule) ----------------
__device__ float g_pre0[(size_t)Bq*Tq*Hq];   // [B*T, H]
__device__ float g_h0[2*BHq];                // double-buffered layer0 state
__device__ float g_p1[2*BHq];                // double-buffered layer1 input preact
__device__ float g_h1[2*BHq];                // double-buffered layer1 state
__device__ float g_z1[Bq*F1q];
__device__ unsigned g_count;
__device__ volatile unsigned g_sense;

// ---------------- packed f32x2 helpers ----------------
__device__ __forceinline__ unsigned long long pack2(float lo, float hi)
{
    unsigned long long v;
    asm("mov.b64 %0, {%1, %2};" : "=l"(v) : "f"(lo), "f"(hi));
    return v;
}
__device__ __forceinline__ void unpack2(unsigned long long v, float &lo, float &hi)
{
    asm("mov.b64 {%0, %1}, %2;" : "=f"(lo), "=f"(hi) : "l"(v));
}
__device__ __forceinline__ void ffma2(unsigned long long &d,
                                      unsigned long long a, unsigned long long b)
{
    asm("fma.rn.f32x2 %0, %1, %2, %0;" : "+l"(d) : "l"(a), "l"(b));
}

// ---------------- grid barrier (sense-reversing, 1 wave resident) ----------------
__device__ __forceinline__ void grid_barrier(unsigned nblk, unsigned &sense)
{
    __syncthreads();
    if (threadIdx.x == 0) {
        unsigned ns = sense ^ 1u;
        if (atomicAdd(&g_count, 1u) == nblk - 1u) {
            g_count = 0u;
            __threadfence();
            g_sense = ns;
        } else {
            while (g_sense != ns) { __nanosleep(64); }
        }
    }
    __syncthreads();
    sense ^= 1u;
}

// ---------------- 64x64 fp32 GEMM tile core:  C = A(M,K) * W(N,K)^T ----------------
// 256 threads, thread (tx,ty) computes 4x4 at (ty*4, tx*4). K multiple of 16.
// Double-buffered smem (1 sync/chunk, gmem prefetch overlapped) + fma.rn.f32x2:
// accumulators paired along rows -> A operand is a free LDS.64 row-pair,
// W needs 4 broadcast packs/k (ALU pipe, overlaps FMA pipe).
__device__ __forceinline__ void gemm64(const float* __restrict__ A, int lda, int m0,
                                       const float* __restrict__ W, int ldw, int n0,
                                       int K, bool cgA,
                                       float* sA, float* sW, float accf[4][4])
{
    const int tid  = threadIdx.x;
    const int tx   = tid & 15, ty = tid >> 4;
    const int lrow = tid >> 2;          // 0..63
    const int lcg  = (tid & 3) << 2;    // 0,4,8,12
    const float* ap = A + (size_t)(m0 + lrow) * lda + lcg;
    const float* wp = W + (size_t)(n0 + lrow) * ldw + lcg;

    unsigned long long acc[2][4];
    #pragma unroll
    for (int i = 0; i < 2; ++i)
        #pragma unroll
        for (int j = 0; j < 4; ++j) acc[i][j] = 0ull;

    // prologue: fetch chunk 0
    float4 av = cgA ? __ldcg((const float4*)ap) : *(const float4*)ap;
    float4 wv = *(const float4*)wp;

    int buf = 0;
    for (int kc = 0; kc < K; kc += 16, buf ^= 1) {
        float* sAb = sA + buf * SCH;
        float* sWb = sW + buf * SCH;
        sAb[(lcg+0)*68 + lrow] = av.x;
        sAb[(lcg+1)*68 + lrow] = av.y;
        sAb[(lcg+2)*68 + lrow] = av.z;
        sAb[(lcg+3)*68 + lrow] = av.w;
        sWb[(lcg+0)*68 + lrow] = wv.x;
        sWb[(lcg+1)*68 + lrow] = wv.y;
        sWb[(lcg+2)*68 + lrow] = wv.z;
        sWb[(lcg+3)*68 + lrow] = wv.w;
        __syncthreads();
        // prefetch next chunk while computing this one (latency hidden)
        if (kc + 16 < K) {
            av = cgA ? __ldcg((const float4*)(ap + kc + 16)) : *(const float4*)(ap + kc + 16);
            wv = *(const float4*)(wp + kc + 16);
        }
        #pragma unroll
        for (int k = 0; k < 16; ++k) {
            const float* ar = sAb + k*68 + (ty << 2);
            unsigned long long a01 = *(const unsigned long long*)ar;        // rows +0,+1
            unsigned long long a23 = *(const unsigned long long*)(ar + 2);  // rows +2,+3
            float4 w = *(const float4*)(sWb + k*68 + (tx << 2));
            unsigned long long b0 = pack2(w.x, w.x);
            unsigned long long b1 = pack2(w.y, w.y);
            unsigned long long b2 = pack2(w.z, w.z);
            unsigned long long b3 = pack2(w.w, w.w);
            ffma2(acc[0][0], a01, b0); ffma2(acc[0][1], a01, b1);
            ffma2(acc[0][2], a01, b2); ffma2(acc[0][3], a01, b3);
            ffma2(acc[1][0], a23, b0); ffma2(acc[1][1], a23, b1);
            ffma2(acc[1][2], a23, b2); ffma2(acc[1][3], a23, b3);
        }
        // no trailing sync needed: next store targets the other buffer, and the
        // next iteration's sync orders it against all warps' current compute.
    }

    #pragma unroll
    for (int i = 0; i < 2; ++i)
        #pragma unroll
        for (int j = 0; j < 4; ++j)
            unpack2(acc[i][j], accf[2*i][j], accf[2*i + 1][j]);
}

// ---------------- kernel A: pre0 = x @ W_ih0^T + b_ih0 + b_hh0 ----------------
__global__ void __launch_bounds__(256) k_pre0(const float* __restrict__ x,
                                              const float* __restrict__ Wih,
                                              const float* __restrict__ bih,
                                              const float* __restrict__ bhh)
{
    __shared__ __align__(16) float sA[2*SCH], sW[2*SCH];
    float acc[4][4];
    const int m0 = blockIdx.y << 6;   // over B*T (2048 tiles)
    const int n0 = blockIdx.x << 6;   // over H (8 tiles)
    gemm64(x, Dq, m0, Wih, Dq, n0, Dq, false, sA, sW, acc);

    const int tx = threadIdx.x & 15, ty = threadIdx.x >> 4;
    const int col = n0 + (tx << 2);
    float4 b1 = *(const float4*)(bih + col);
    float4 b2 = *(const float4*)(bhh + col);
    #pragma unroll
    for (int i = 0; i < 4; ++i) {
        int row = m0 + (ty << 2) + i;
        float4 o;
        o.x = acc[i][0] + b1.x + b2.x;
        o.y = acc[i][1] + b1.y + b2.y;
        o.z = acc[i][2] + b1.z + b2.z;
        o.w = acc[i][3] + b1.w + b2.w;
        *(float4*)(g_pre0 + (size_t)row*Hq + col) = o;
    }
}

// ---------------- reset barrier state (runs before each scan) ----------------
__global__ void k_reset()
{
    g_count = 0u;
    g_sense = 0u;
}

// ---------------- kernel B: persistent pipelined 2-layer scan ----------------
// 96 blocks = 3 groups x 32 tiles (64x64). 514 rounds, grid barrier each round.
//  G0 @ round r (r<T):    h0_r    = tanh(pre0[:,r,:] + h0_{r-1} @ W_hh0^T)
//  G1 @ round r (1<=r<=T):p1_{r-1}= h0_{r-1} @ W_ih1^T + b_ih1 + b_hh1
//  G2 @ round r (r>=2):   h1_{r-2}= tanh(p1_{r-2} + h1_{r-3} @ W_hh1^T)
__global__ void __launch_bounds__(256) k_scan(const float* __restrict__ Whh0,
                                              const float* __restrict__ Wih1,
                                              const float* __restrict__ bih1,
                                              const float* __restrict__ bhh1,
                                              const float* __restrict__ Whh1)
{
    __shared__ __align__(16) float sA[2*SCH], sW[2*SCH];
    const int tid   = threadIdx.x;
    const int blk   = blockIdx.x;
    const int group = blk >> 5;        // 0,1,2
    const int tile  = blk & 31;
    const int m0    = (tile & 3) << 6; // B rows
    const int n0    = (tile >> 2) << 6;// H cols
    const int tx = tid & 15, ty = tid >> 4;
    unsigned sense = 0u;

    // zero the t=-1 parity buffers (buf index ((-1)&1)==1)
    for (int i = blk*256 + tid; i < BHq; i += NBLK_SCAN*256) {
        g_h0[BHq + i] = 0.f;
        g_h1[BHq + i] = 0.f;
    }
    __threadfence();
    grid_barrier(gridDim.x, sense);

    for (int r = 0; r < Tq + 2; ++r) {
        if (group == 0) {
            if (r < Tq) {
                float acc[4][4];
                const float* A = g_h0 + (size_t)((r+1)&1)*BHq;   // h0_{r-1}
                gemm64(A, Hq, m0, Whh0, Hq, n0, Hq, true, sA, sW, acc);
                float* dst = g_h0 + (size_t)(r&1)*BHq;
                const int col = n0 + (tx << 2);
                #pragma unroll
                for (int i = 0; i < 4; ++i) {
                    int row = m0 + (ty << 2) + i;
                    float4 p = __ldcg((const float4*)(g_pre0 + ((size_t)row*Tq + r)*Hq + col));
                    float4 o;
                    o.x = tanhf(acc[i][0] + p.x);
                    o.y = tanhf(acc[i][1] + p.y);
                    o.z = tanhf(acc[i][2] + p.z);
                    o.w = tanhf(acc[i][3] + p.w);
                    *(float4*)(dst + (size_t)row*Hq + col) = o;
                }
            }
        } else if (group == 1) {
            if (r >= 1 && r <= Tq) {
                float acc[4][4];
                const float* A = g_h0 + (size_t)((r+1)&1)*BHq;   // h0_{r-1}
                gemm64(A, Hq, m0, Wih1, Hq, n0, Hq, true, sA, sW, acc);
                float* dst = g_p1 + (size_t)((r+1)&1)*BHq;       // p1_{r-1}
                const int col = n0 + (tx << 2);
                float4 b1 = *(const float4*)(bih1 + col);
                float4 b2 = *(const float4*)(bhh1 + col);
                #pragma unroll
                for (int i = 0; i < 4; ++i) {
                    int row = m0 + (ty << 2) + i;
                    float4 o;
                    o.x = acc[i][0] + b1.x + b2.x;
                    o.y = acc[i][1] + b1.y + b2.y;
                    o.z = acc[i][2] + b1.z + b2.z;
                    o.w = acc[i][3] + b1.w + b2.w;
                    *(float4*)(dst + (size_t)row*Hq + col) = o;
                }
            }
        } else {
            if (r >= 2) {
                const int t = r - 2;
                float acc[4][4];
                const float* A = g_h1 + (size_t)((t+1)&1)*BHq;   // h1_{t-1}
                gemm64(A, Hq, m0, Whh1, Hq, n0, Hq, true, sA, sW, acc);
                float* dst = g_h1 + (size_t)(t&1)*BHq;
                const float* pin = g_p1 + (size_t)(t&1)*BHq;
                const int col = n0 + (tx << 2);
                #pragma unroll
                for (int i = 0; i < 4; ++i) {
                    int row = m0 + (ty << 2) + i;
                    float4 p = __ldcg((const float4*)(pin + (size_t)row*Hq + col));
                    float4 o;
                    o.x = tanhf(acc[i][0] + p.x);
                    o.y = tanhf(acc[i][1] + p.y);
                    o.z = tanhf(acc[i][2] + p.z);
                    o.w = tanhf(acc[i][3] + p.w);
                    *(float4*)(dst + (size_t)row*Hq + col) = o;
                }
            }
        }
        __threadfence();
        grid_barrier(gridDim.x, sense);
    }
}

// ---------------- head: z1 = relu(h1_last @ Wf1^T + bf1) ----------------
__global__ void __launch_bounds__(256) k_fc1(const float* __restrict__ Wf1,
                                             const float* __restrict__ bf1)
{
    __shared__ __align__(16) float sA[2*SCH], sW[2*SCH];
    float acc[4][4];
    const int m0 = blockIdx.y << 6;   // B (4)
    const int n0 = blockIdx.x << 6;   // F1 (2)
    const float* A = g_h1 + (size_t)((Tq-1)&1)*BHq;  // h1_{511} lives in buf 1
    gemm64(A, Hq, m0, Wf1, Hq, n0, Hq, false, sA, sW, acc);

    const int tx = threadIdx.x & 15, ty = threadIdx.x >> 4;
    const int col = n0 + (tx << 2);
    float4 b = *(const float4*)(bf1 + col);
    #pragma unroll
    for (int i = 0; i < 4; ++i) {
        int row = m0 + (ty << 2) + i;
        float4 o;
        o.x = fmaxf(acc[i][0] + b.x, 0.f);
        o.y = fmaxf(acc[i][1] + b.y, 0.f);
        o.z = fmaxf(acc[i][2] + b.z, 0.f);
        o.w = fmaxf(acc[i][3] + b.w, 0.f);
        *(float4*)(g_z1 + (size_t)row*F1q + col) = o;
    }
}

// ---------------- head: out = z1 @ Wf2^T + bf2 ----------------
__global__ void __launch_bounds__(256) k_fc2(const float* __restrict__ Wf2,
                                             const float* __restrict__ bf2,
                                             float* __restrict__ out)
{
    __shared__ __align__(16) float sA[2*SCH], sW[2*SCH];
    float acc[4][4];
    const int m0 = blockIdx.y << 6;   // B (4)
    const int n0 = 0;                 // O = 64, single tile
    gemm64(g_z1, F1q, m0, Wf2, F1q, n0, F1q, false, sA, sW, acc);

    const int tx = threadIdx.x & 15, ty = threadIdx.x >> 4;
    const int col = n0 + (tx << 2);
    float4 b = *(const float4*)(bf2 + col);
    #pragma unroll
    for (int i = 0; i < 4; ++i) {
        int row = m0 + (ty << 2) + i;
        float4 o;
        o.x = acc[i][0] + b.x;
        o.y = acc[i][1] + b.y;
        o.z = acc[i][2] + b.z;
        o.w = acc[i][3] + b.w;
        *(float4*)(out + (size_t)row*Oq + col) = o;
    }
}

// ---------------- launch ----------------
extern "C" void kernel_launch(void* const* d_in, const int* in_sizes, int n_in,
                              void* d_out, int out_size)
{
    (void)in_sizes; (void)n_in; (void)out_size;
    const float* x    = (const float*)d_in[0];
    const float* Wih0 = (const float*)d_in[1];
    const float* Whh0 = (const float*)d_in[2];
    const float* bih0 = (const float*)d_in[3];
    const float* bhh0 = (const float*)d_in[4];
    const float* Wih1 = (const float*)d_in[5];
    const float* Whh1 = (const float*)d_in[6];
    const float* bih1 = (const float*)d_in[7];
    const float* bhh1 = (const float*)d_in[8];
    const float* Wf1  = (const float*)d_in[9];
    const float* bf1  = (const float*)d_in[10];
    const float* Wf2  = (const float*)d_in[11];
    const float* bf2  = (const float*)d_in[12];
    float* out = (float*)d_out;

    k_pre0<<<dim3(Hq/64, (Bq*Tq)/64), 256>>>(x, Wih0, bih0, bhh0);
    k_reset<<<1, 1>>>();
    k_scan<<<NBLK_SCAN, 256>>>(Whh0, Wih1, bih1, bhh1, Whh1);
    k_fc1<<<dim3(F1q/64, Bq/64), 256>>>(Wf1, bf1);
    k_fc2<<<dim3(1, Bq/64), 256>>>(Wf2, bf2, out);
}

// round 5
// speedup vs baseline: 1.5383x; 1.1708x over previous
#include <cuda_runtime.h>
#include <math.h>

typedef unsigned long long ull;

#define Bq   256
#define Tq   512
#define Dq   256
#define Hq   512
#define F1q  128
#define Oq   64
#define BHq  (Bq*Hq)
#define NBLK_SCAN 128
#define SCH  (16*68)          // one A smem chunk: 16 k-slices x 68-stride
#define WST  68               // persistent W smem stride (floats), 16B-aligned rows
#define SMEM_SCAN ((Hq*WST + 2*SCH) * 4)   // 512*68 + 2*16*68 floats -> 147,968 B

// ---------------- scratch (device globals: allocation-free rule) ----------------
__device__ float g_pre0r[4*BHq];             // 4-slot ring of per-step preactivations (2 MB)
__device__ float g_h0[2*BHq];                // double-buffered layer0 state
__device__ float g_p1[2*BHq];                // double-buffered layer1 input preact
__device__ float g_h1[2*BHq];                // double-buffered layer1 state
__device__ float g_z1[Bq*F1q];
__device__ unsigned g_count;
__device__ volatile unsigned g_sense;

// ---------------- packed f32x2 helpers ----------------
__device__ __forceinline__ ull pack2(float lo, float hi)
{
    ull v;
    asm("mov.b64 %0, {%1, %2};" : "=l"(v) : "f"(lo), "f"(hi));
    return v;
}
__device__ __forceinline__ void unpack2(ull v, float &lo, float &hi)
{
    asm("mov.b64 {%0, %1}, %2;" : "=f"(lo), "=f"(hi) : "l"(v));
}
__device__ __forceinline__ void ffma2(ull &d, ull a, ull b)
{
    asm("fma.rn.f32x2 %0, %1, %2, %0;" : "+l"(d) : "l"(a), "l"(b));
}

// ---------------- grid barrier (sense-reversing, 1 wave resident) ----------------
__device__ __forceinline__ void grid_barrier(unsigned nblk, unsigned &sense)
{
    __syncthreads();
    if (threadIdx.x == 0) {
        unsigned ns = sense ^ 1u;
        if (atomicAdd(&g_count, 1u) == nblk - 1u) {
            g_count = 0u;
            __threadfence();
            g_sense = ns;
        } else {
            while (g_sense != ns) { __nanosleep(32); }
        }
    }
    __syncthreads();
    sense ^= 1u;
}

// ======== scan GEMM core with persistent-W-in-smem:  C64x64 = A(:,K) * Wsmem^T ========
// 256 threads, thread (tx,ty) owns 4x4 at (ty*4, tx*4). A prefetched 2 chunks deep.
// sW layout: sW[k*WST + n], n in 0..63 (written once per kernel, reused all rounds).
__device__ __forceinline__ void gemm64_wp(const float* __restrict__ A, int lda, int m0,
                                          const float* __restrict__ sW, int K,
                                          float* sA, float accf[4][4])
{
    const int tid  = threadIdx.x;
    const int tx   = tid & 15, ty = tid >> 4;
    const int lrow = tid >> 2;          // 0..63
    const int lcg  = (tid & 3) << 2;    // 0,4,8,12
    const float* ap = A + (size_t)(m0 + lrow) * lda + lcg;

    ull acc[2][4];
    #pragma unroll
    for (int i = 0; i < 2; ++i)
        #pragma unroll
        for (int j = 0; j < 4; ++j) acc[i][j] = 0ull;

    // prologue: prefetch chunks 0 and 1 (K >= 32 always here)
    float4 av0 = __ldcg((const float4*)ap);
    float4 av1 = __ldcg((const float4*)(ap + 16));

    int buf = 0;
    for (int kc = 0; kc < K; kc += 16, buf ^= 1) {
        float* sAb = sA + buf * SCH;
        sAb[(lcg+0)*68 + lrow] = av0.x;
        sAb[(lcg+1)*68 + lrow] = av0.y;
        sAb[(lcg+2)*68 + lrow] = av0.z;
        sAb[(lcg+3)*68 + lrow] = av0.w;
        __syncthreads();
        av0 = av1;
        if (kc + 32 < K)
            av1 = __ldcg((const float4*)(ap + kc + 32));
        const float* sWk = sW + kc * WST;
        #pragma unroll
        for (int k = 0; k < 16; ++k) {
            const float* ar = sAb + k*68 + (ty << 2);
            ull a01 = *(const ull*)ar;        // rows +0,+1
            ull a23 = *(const ull*)(ar + 2);  // rows +2,+3
            float4 w = *(const float4*)(sWk + k*WST + (tx << 2));
            ull b0 = pack2(w.x, w.x);
            ull b1 = pack2(w.y, w.y);
            ull b2 = pack2(w.z, w.z);
            ull b3 = pack2(w.w, w.w);
            ffma2(acc[0][0], a01, b0); ffma2(acc[0][1], a01, b1);
            ffma2(acc[0][2], a01, b2); ffma2(acc[0][3], a01, b3);
            ffma2(acc[1][0], a23, b0); ffma2(acc[1][1], a23, b1);
            ffma2(acc[1][2], a23, b2); ffma2(acc[1][3], a23, b3);
        }
        // next store targets the other buffer; its safety is ordered by the next sync.
    }

    #pragma unroll
    for (int i = 0; i < 2; ++i)
        #pragma unroll
        for (int j = 0; j < 4; ++j)
            unpack2(acc[i][j], accf[2*i][j], accf[2*i + 1][j]);
}

// preload one 64-row W tile (rows n0..n0+63, K cols) into sW[k*WST + n], coalesced on gmem
__device__ __forceinline__ void preload_W(const float* __restrict__ W, int ldw, int n0,
                                          int K, float* sW)
{
    const int KQ = K >> 2;
    for (int i = threadIdx.x; i < (KQ << 6); i += 256) {
        int n  = i / KQ;
        int k4 = i - n * KQ;
        float4 v = *(const float4*)(W + (size_t)(n0 + n) * ldw + (k4 << 2));
        sW[(4*k4+0)*WST + n] = v.x;
        sW[(4*k4+1)*WST + n] = v.y;
        sW[(4*k4+2)*WST + n] = v.z;
        sW[(4*k4+3)*WST + n] = v.w;
    }
}

// ---------------- legacy chunked GEMM core (for the tiny head kernels) ----------------
__device__ __forceinline__ void gemm64s(const float* __restrict__ A, int lda, int m0,
                                        const float* __restrict__ W, int ldw, int n0,
                                        int K, bool cgA,
                                        float* sA, float* sW, float accf[4][4])
{
    const int tid  = threadIdx.x;
    const int tx   = tid & 15, ty = tid >> 4;
    const int lrow = tid >> 2;
    const int lcg  = (tid & 3) << 2;
    const float* ap = A + (size_t)(m0 + lrow) * lda + lcg;
    const float* wp = W + (size_t)(n0 + lrow) * ldw + lcg;

    ull acc[2][4];
    #pragma unroll
    for (int i = 0; i < 2; ++i)
        #pragma unroll
        for (int j = 0; j < 4; ++j) acc[i][j] = 0ull;

    float4 av = cgA ? __ldcg((const float4*)ap) : *(const float4*)ap;
    float4 wv = *(const float4*)wp;

    int buf = 0;
    for (int kc = 0; kc < K; kc += 16, buf ^= 1) {
        float* sAb = sA + buf * SCH;
        float* sWb = sW + buf * SCH;
        sAb[(lcg+0)*68 + lrow] = av.x;
        sAb[(lcg+1)*68 + lrow] = av.y;
        sAb[(lcg+2)*68 + lrow] = av.z;
        sAb[(lcg+3)*68 + lrow] = av.w;
        sWb[(lcg+0)*68 + lrow] = wv.x;
        sWb[(lcg+1)*68 + lrow] = wv.y;
        sWb[(lcg+2)*68 + lrow] = wv.z;
        sWb[(lcg+3)*68 + lrow] = wv.w;
        __syncthreads();
        if (kc + 16 < K) {
            av = cgA ? __ldcg((const float4*)(ap + kc + 16)) : *(const float4*)(ap + kc + 16);
            wv = *(const float4*)(wp + kc + 16);
        }
        #pragma unroll
        for (int k = 0; k < 16; ++k) {
            const float* ar = sAb + k*68 + (ty << 2);
            ull a01 = *(const ull*)ar;
            ull a23 = *(const ull*)(ar + 2);
            float4 w = *(const float4*)(sWb + k*68 + (tx << 2));
            ull b0 = pack2(w.x, w.x);
            ull b1 = pack2(w.y, w.y);
            ull b2 = pack2(w.z, w.z);
            ull b3 = pack2(w.w, w.w);
            ffma2(acc[0][0], a01, b0); ffma2(acc[0][1], a01, b1);
            ffma2(acc[0][2], a01, b2); ffma2(acc[0][3], a01, b3);
            ffma2(acc[1][0], a23, b0); ffma2(acc[1][1], a23, b1);
            ffma2(acc[1][2], a23, b2); ffma2(acc[1][3], a23, b3);
        }
    }

    #pragma unroll
    for (int i = 0; i < 2; ++i)
        #pragma unroll
        for (int j = 0; j < 4; ++j)
            unpack2(acc[i][j], accf[2*i][j], accf[2*i + 1][j]);
}

// ---------------- reset barrier state ----------------
__global__ void k_reset()
{
    g_count = 0u;
    g_sense = 0u;
}

// ========================= persistent fused 2-layer scan =========================
// 128 blocks = 4 groups x 32 tiles (64x64). 515 rounds, grid barrier each round.
//  G3 @ r (r<T):        pre0[t=r]  = x[:,r,:] @ W_ih0^T + b_ih0 + b_hh0   (ring slot r&3)
//  G0 @ r (1<=r<=T):    h0[t=r-1]  = tanh(pre0[r-1] + h0[r-2] @ W_hh0^T)
//  G1 @ r (2<=r<=T+1):  p1[t=r-2]  = h0[r-2] @ W_ih1^T + b_ih1 + b_hh1
//  G2 @ r (3<=r<=T+2):  h1[t=r-3]  = tanh(p1[r-3] + h1[r-4] @ W_hh1^T)
__global__ void __launch_bounds__(256) k_scan(const float* __restrict__ x,
                                              const float* __restrict__ Wih0,
                                              const float* __restrict__ bih0,
                                              const float* __restrict__ bhh0,
                                              const float* __restrict__ Whh0,
                                              const float* __restrict__ Wih1,
                                              const float* __restrict__ bih1,
                                              const float* __restrict__ bhh1,
                                              const float* __restrict__ Whh1)
{
    extern __shared__ __align__(16) float smem[];
    float* sW = smem;                 // persistent W tile: up to 512*WST floats
    float* sA = smem + Hq*WST;        // double-buffered A chunks: 2*SCH floats

    const int tid   = threadIdx.x;
    const int blk   = blockIdx.x;
    const int group = blk >> 5;        // 0..3
    const int tile  = blk & 31;
    const int m0    = (tile & 3) << 6; // rows (B)
    const int n0    = (tile >> 2) << 6;// cols (H)
    const int tx = tid & 15, ty = tid >> 4;
    unsigned sense = 0u;

    // one-time: load this block's weight tile into smem
    if      (group == 0) preload_W(Whh0, Hq, n0, Hq, sW);
    else if (group == 1) preload_W(Wih1, Hq, n0, Hq, sW);
    else if (group == 2) preload_W(Whh1, Hq, n0, Hq, sW);
    else                 preload_W(Wih0, Dq, n0, Dq, sW);

    // zero the t=-1 parity buffers (parity of t=-1 is 1)
    for (int i = blk*256 + tid; i < BHq; i += NBLK_SCAN*256) {
        g_h0[BHq + i] = 0.f;
        g_h1[BHq + i] = 0.f;
    }
    __threadfence();
    grid_barrier(gridDim.x, sense);

    const int col = n0 + (tx << 2);

    for (int r = 0; r < Tq + 3; ++r) {
        if (group == 3) {
            if (r < Tq) {
                float acc[4][4];
                gemm64_wp(x + (size_t)r*Dq, Tq*Dq, m0, sW, Dq, sA, acc);
                float* dst = g_pre0r + (size_t)(r & 3)*BHq;
                float4 b1 = *(const float4*)(bih0 + col);
                float4 b2 = *(const float4*)(bhh0 + col);
                #pragma unroll
                for (int i = 0; i < 4; ++i) {
                    int row = m0 + (ty << 2) + i;
                    float4 o;
                    o.x = acc[i][0] + b1.x + b2.x;
                    o.y = acc[i][1] + b1.y + b2.y;
                    o.z = acc[i][2] + b1.z + b2.z;
                    o.w = acc[i][3] + b1.w + b2.w;
                    *(float4*)(dst + (size_t)row*Hq + col) = o;
                }
            }
        } else if (group == 0) {
            if (r >= 1 && r <= Tq) {
                const int t = r - 1;
                float acc[4][4];
                const float* A = g_h0 + (size_t)((t+1)&1)*BHq;   // h0[t-1]
                gemm64_wp(A, Hq, m0, sW, Hq, sA, acc);
                float* dst = g_h0 + (size_t)(t&1)*BHq;
                const float* pin = g_pre0r + (size_t)(t & 3)*BHq;
                #pragma unroll
                for (int i = 0; i < 4; ++i) {
                    int row = m0 + (ty << 2) + i;
                    float4 p = __ldcg((const float4*)(pin + (size_t)row*Hq + col));
                    float4 o;
                    o.x = tanhf(acc[i][0] + p.x);
                    o.y = tanhf(acc[i][1] + p.y);
                    o.z = tanhf(acc[i][2] + p.z);
                    o.w = tanhf(acc[i][3] + p.w);
                    *(float4*)(dst + (size_t)row*Hq + col) = o;
                }
            }
        } else if (group == 1) {
            if (r >= 2 && r <= Tq + 1) {
                const int t = r - 2;
                float acc[4][4];
                const float* A = g_h0 + (size_t)(t&1)*BHq;       // h0[t]
                gemm64_wp(A, Hq, m0, sW, Hq, sA, acc);
                float* dst = g_p1 + (size_t)(t&1)*BHq;
                float4 b1 = *(const float4*)(bih1 + col);
                float4 b2 = *(const float4*)(bhh1 + col);
                #pragma unroll
                for (int i = 0; i < 4; ++i) {
                    int row = m0 + (ty << 2) + i;
                    float4 o;
                    o.x = acc[i][0] + b1.x + b2.x;
                    o.y = acc[i][1] + b1.y + b2.y;
                    o.z = acc[i][2] + b1.z + b2.z;
                    o.w = acc[i][3] + b1.w + b2.w;
                    *(float4*)(dst + (size_t)row*Hq + col) = o;
                }
            }
        } else {
            if (r >= 3) {
                const int t = r - 3;
                float acc[4][4];
                const float* A = g_h1 + (size_t)((t+1)&1)*BHq;   // h1[t-1]
                gemm64_wp(A, Hq, m0, sW, Hq, sA, acc);
                float* dst = g_h1 + (size_t)(t&1)*BHq;
                const float* pin = g_p1 + (size_t)(t&1)*BHq;
                #pragma unroll
                for (int i = 0; i < 4; ++i) {
                    int row = m0 + (ty << 2) + i;
                    float4 p = __ldcg((const float4*)(pin + (size_t)row*Hq + col));
                    float4 o;
                    o.x = tanhf(acc[i][0] + p.x);
                    o.y = tanhf(acc[i][1] + p.y);
                    o.z = tanhf(acc[i][2] + p.z);
                    o.w = tanhf(acc[i][3] + p.w);
                    *(float4*)(dst + (size_t)row*Hq + col) = o;
                }
            }
        }
        __threadfence();
        grid_barrier(gridDim.x, sense);
    }
}

// ---------------- head: z1 = relu(h1_last @ Wf1^T + bf1) ----------------
__global__ void __launch_bounds__(256) k_fc1(const float* __restrict__ Wf1,
                                             const float* __restrict__ bf1)
{
    __shared__ __align__(16) float sA[2*SCH], sW[2*SCH];
    float acc[4][4];
    const int m0 = blockIdx.y << 6;   // B (4)
    const int n0 = blockIdx.x << 6;   // F1 (2)
    const float* A = g_h1 + (size_t)((Tq-1)&1)*BHq;  // h1[511] lives in buf 1
    gemm64s(A, Hq, m0, Wf1, Hq, n0, Hq, true, sA, sW, acc);

    const int tx = threadIdx.x & 15, ty = threadIdx.x >> 4;
    const int col = n0 + (tx << 2);
    float4 b = *(const float4*)(bf1 + col);
    #pragma unroll
    for (int i = 0; i < 4; ++i) {
        int row = m0 + (ty << 2) + i;
        float4 o;
        o.x = fmaxf(acc[i][0] + b.x, 0.f);
        o.y = fmaxf(acc[i][1] + b.y, 0.f);
        o.z = fmaxf(acc[i][2] + b.z, 0.f);
        o.w = fmaxf(acc[i][3] + b.w, 0.f);
        *(float4*)(g_z1 + (size_t)row*F1q + col) = o;
    }
}

// ---------------- head: out = z1 @ Wf2^T + bf2 ----------------
__global__ void __launch_bounds__(256) k_fc2(const float* __restrict__ Wf2,
                                             const float* __restrict__ bf2,
                                             float* __restrict__ out)
{
    __shared__ __align__(16) float sA[2*SCH], sW[2*SCH];
    float acc[4][4];
    const int m0 = blockIdx.y << 6;   // B (4)
    const int n0 = 0;                 // O = 64, single tile
    gemm64s(g_z1, F1q, m0, Wf2, F1q, n0, F1q, true, sA, sW, acc);

    const int tx = threadIdx.x & 15, ty = threadIdx.x >> 4;
    const int col = n0 + (tx << 2);
    float4 b = *(const float4*)(bf2 + col);
    #pragma unroll
    for (int i = 0; i < 4; ++i) {
        int row = m0 + (ty << 2) + i;
        float4 o;
        o.x = acc[i][0] + b.x;
        o.y = acc[i][1] + b.y;
        o.z = acc[i][2] + b.z;
        o.w = acc[i][3] + b.w;
        *(float4*)(out + (size_t)row*Oq + col) = o;
    }
}

// ---------------- launch ----------------
extern "C" void kernel_launch(void* const* d_in, const int* in_sizes, int n_in,
                              void* d_out, int out_size)
{
    (void)in_sizes; (void)n_in; (void)out_size;
    const float* x    = (const float*)d_in[0];
    const float* Wih0 = (const float*)d_in[1];
    const float* Whh0 = (const float*)d_in[2];
    const float* bih0 = (const float*)d_in[3];
    const float* bhh0 = (const float*)d_in[4];
    const float* Wih1 = (const float*)d_in[5];
    const float* Whh1 = (const float*)d_in[6];
    const float* bih1 = (const float*)d_in[7];
    const float* bhh1 = (const float*)d_in[8];
    const float* Wf1  = (const float*)d_in[9];
    const float* bf1  = (const float*)d_in[10];
    const float* Wf2  = (const float*)d_in[11];
    const float* bf2  = (const float*)d_in[12];
    float* out = (float*)d_out;

    cudaFuncSetAttribute(k_scan, cudaFuncAttributeMaxDynamicSharedMemorySize, SMEM_SCAN);

    k_reset<<<1, 1>>>();
    k_scan<<<NBLK_SCAN, 256, SMEM_SCAN>>>(x, Wih0, bih0, bhh0, Whh0,
                                          Wih1, bih1, bhh1, Whh1);
    k_fc1<<<dim3(F1q/64, Bq/64), 256>>>(Wf1, bf1);
    k_fc2<<<dim3(1, Bq/64), 256>>>(Wf2, bf2, out);
}